// round 11
// baseline (speedup 1.0000x reference)
#include <cuda_runtime.h>
#include <cuda_bf16.h>
#include <cstdint>

using bf16 = __nv_bfloat16;

constexpr int B_  = 4;
constexpr int N_  = 4096;
constexpr int M_  = 1024;
constexpr int QD_ = 320;
constexpr int CD_ = 768;
constexpr int ID_ = 512;
constexpr int H_  = 8;
// softmax scale with log2(e) folded: scores land in log2 domain, softmax via exp2
constexpr float QSCALE_ = 0.125f * 1.4426950408889634f;

// ---------------------------------------------------------------------------
// Device-global scratch (hi/lo bf16 pairs)
// ---------------------------------------------------------------------------
__device__ bf16 g_xhi[16384 * 320], g_xlo[16384 * 320];
__device__ bf16 g_chi[4096 * 768],  g_clo[4096 * 768];
__device__ bf16 g_wqhi[320 * 512],  g_wqlo[320 * 512];
__device__ bf16 g_wkhi[768 * 512],  g_wklo[768 * 512];
__device__ bf16 g_wvhi[768 * 512],  g_wvlo[768 * 512];
__device__ bf16 g_wohi[512 * 320],  g_wolo[512 * 320];
__device__ bf16 g_qhi[16384 * 512], g_qlo[16384 * 512];  // head-major [b,h,n,64]
__device__ bf16 g_khi[4096 * 512],  g_klo[4096 * 512];   // head-major [b,h,m,64]
__device__ bf16 g_vhi[4096 * 512],  g_vlo[4096 * 512];
__device__ bf16 g_ohi[16384 * 512], g_olo[16384 * 512];  // row-major [b*n, 512]

// ---------------------------------------------------------------------------
// Helpers
// ---------------------------------------------------------------------------
__device__ __forceinline__ uint32_t smem_u32(const void* p) {
    return (uint32_t)__cvta_generic_to_shared(p);
}
__device__ __forceinline__ uint32_t pk2(bf16 lo, bf16 hi) {
    return ((uint32_t)__bfloat16_as_ushort(hi) << 16) |
            (uint32_t)__bfloat16_as_ushort(lo);
}
__device__ __forceinline__ void split2(float x, float y, uint32_t& h, uint32_t& l) {
    bf16 xh = __float2bfloat16_rn(x), yh = __float2bfloat16_rn(y);
    h = pk2(xh, yh);
    l = pk2(__float2bfloat16_rn(x - __bfloat162float(xh)),
            __float2bfloat16_rn(y - __bfloat162float(yh)));
}
__device__ __forceinline__ float ex2(float x) {
    float y;
    asm("ex2.approx.ftz.f32 %0, %1;" : "=f"(y) : "f"(x));
    return y;
}
__device__ __forceinline__ void mma_bf16(float* d, const uint32_t* a, const uint32_t* b) {
    asm volatile(
        "mma.sync.aligned.m16n8k16.row.col.f32.bf16.bf16.f32 "
        "{%0,%1,%2,%3}, {%4,%5,%6,%7}, {%8,%9}, {%0,%1,%2,%3};\n"
        : "+f"(d[0]), "+f"(d[1]), "+f"(d[2]), "+f"(d[3])
        : "r"(a[0]), "r"(a[1]), "r"(a[2]), "r"(a[3]), "r"(b[0]), "r"(b[1]));
}
__device__ __forceinline__ void ldsm4(uint32_t* r, uint32_t a) {
    asm volatile("ldmatrix.sync.aligned.m8n8.x4.shared.b16 {%0,%1,%2,%3}, [%4];\n"
        : "=r"(r[0]), "=r"(r[1]), "=r"(r[2]), "=r"(r[3]) : "r"(a));
}
__device__ __forceinline__ void ldsm4t(uint32_t* r, uint32_t a) {
    asm volatile("ldmatrix.sync.aligned.m8n8.x4.trans.shared.b16 {%0,%1,%2,%3}, [%4];\n"
        : "=r"(r[0]), "=r"(r[1]), "=r"(r[2]), "=r"(r[3]) : "r"(a));
}
__device__ __forceinline__ uint32_t tile_addr(uint32_t base, int row, int cb, int cpr) {
    return base + (uint32_t)((row * cpr + (cb ^ (row & 7))) * 16);
}
__device__ __forceinline__ void cp_async16(uint32_t dst, const void* src) {
    asm volatile("cp.async.ca.shared.global [%0], [%1], 16;\n" :: "r"(dst), "l"(src));
}
__device__ __forceinline__ void cp_commit() {
    asm volatile("cp.async.commit_group;\n");
}
template<int NW> __device__ __forceinline__ void cp_wait() {
    asm volatile("cp.async.wait_group %0;\n" :: "n"(NW));
}

// ---------------------------------------------------------------------------
// Merged split kernels (2 launches total)
// ---------------------------------------------------------------------------
__device__ __forceinline__ void split4(const float4* src, uint2* hi, uint2* lo, int i) {
    float4 v = src[i];
    uint32_t h0, l0, h1, l1;
    split2(v.x, v.y, h0, l0);
    split2(v.z, v.w, h1, l1);
    hi[i] = make_uint2(h0, h1);
    lo[i] = make_uint2(l0, l1);
}
__global__ void split_inputs(const float4* __restrict__ x, const float4* __restrict__ c)
{
    int i = blockIdx.x * blockDim.x + threadIdx.x;
    if (blockIdx.y == 0) {
        if (i < 16384 * 320 / 4) split4(x, (uint2*)g_xhi, (uint2*)g_xlo, i);
    } else {
        if (i < 4096 * 768 / 4)  split4(c, (uint2*)g_chi, (uint2*)g_clo, i);
    }
}
__global__ void split_weights(const float4* __restrict__ wq, const float4* __restrict__ wk,
                              const float4* __restrict__ wv, const float4* __restrict__ wo)
{
    int i = blockIdx.x * blockDim.x + threadIdx.x;
    switch (blockIdx.y) {
    case 0: if (i < 320 * 512 / 4) split4(wq, (uint2*)g_wqhi, (uint2*)g_wqlo, i); break;
    case 1: if (i < 768 * 512 / 4) split4(wk, (uint2*)g_wkhi, (uint2*)g_wklo, i); break;
    case 2: if (i < 768 * 512 / 4) split4(wv, (uint2*)g_wvhi, (uint2*)g_wvlo, i); break;
    default: if (i < 512 * 320 / 4) split4(wo, (uint2*)g_wohi, (uint2*)g_wolo, i); break;
    }
}

// ---------------------------------------------------------------------------
// bf16x3 GEMM, BK=32, cp.async SINGLE-SYNC double-buffered pipeline.
// __launch_bounds__(128,4): regs<=128 -> 4 CTAs/SM.
// blockIdx.z selects (B, O) operand pair -> k-proj and v-proj in ONE launch.
// ---------------------------------------------------------------------------
template<int BM, int BN, int EPI>
__global__ void __launch_bounds__(128, 4) gemm_bf3(
    const bf16* __restrict__ Ahi, const bf16* __restrict__ Alo,
    const bf16* __restrict__ Bhi, const bf16* __restrict__ Blo,
    const bf16* __restrict__ Bhi2, const bf16* __restrict__ Blo2,
    const float* __restrict__ bias, float* __restrict__ Cf,
    bf16* __restrict__ Ohi, bf16* __restrict__ Olo,
    bf16* __restrict__ Ohi2, bf16* __restrict__ Olo2,
    int Ndim, int Kdim, int seq, float scale)
{
    constexpr int WR = BM / 32, WC = BN / 64, NT = WR * WC * 32;
    constexpr int BCH = BN / 8;
    constexpr int AH_BYTES = BM * 5 * 16;
    constexpr int BH_BYTES = 32 * BCH * 16;
    constexpr int STAGE = 2 * AH_BYTES + 2 * BH_BYTES;

    extern __shared__ char smc[];
    const uint32_t sbase = smem_u32(smc);
    const int tid = threadIdx.x, w = tid >> 5, lane = tid & 31;
    const int wr = w % WR, wc = w / WR;
    const int bm0 = blockIdx.y * BM, bn0 = blockIdx.x * BN;
    const int g = lane >> 2, t = lane & 3;

    const bf16* bhi = (blockIdx.z == 0) ? Bhi : Bhi2;
    const bf16* blo = (blockIdx.z == 0) ? Blo : Blo2;
    bf16* ohi = (blockIdx.z == 0) ? Ohi : Ohi2;
    bf16* olo = (blockIdx.z == 0) ? Olo : Olo2;

    float acc[2][8][4];
    #pragma unroll
    for (int a = 0; a < 2; a++)
        #pragma unroll
        for (int i = 0; i < 8; i++)
            #pragma unroll
            for (int j = 0; j < 4; j++) acc[a][i][j] = 0.0f;

    auto issue = [&](int k0, int stage) {
        uint32_t sb = sbase + (uint32_t)(stage * STAGE);
        for (int i = tid; i < BM * 4 * 2; i += NT) {
            int half = i >= BM * 4;
            int rem = i - half * BM * 4;
            int r = rem >> 2, cb = rem & 3;
            const bf16* src = (half ? Alo : Ahi) + (size_t)(bm0 + r) * Kdim + k0 + cb * 8;
            cp_async16(sb + (uint32_t)(half * AH_BYTES) +
                       (uint32_t)((r * 5 + cb) * 16), src);
        }
        for (int i = tid; i < 32 * BCH * 2; i += NT) {
            int half = i >= 32 * BCH;
            int rem = i - half * 32 * BCH;
            int r = rem / BCH, cb = rem - r * BCH;
            const bf16* src = (half ? blo : bhi) + (size_t)(k0 + r) * Ndim + bn0 + cb * 8;
            cp_async16(sb + (uint32_t)(2 * AH_BYTES + half * BH_BYTES) +
                       (uint32_t)((r * BCH + (cb ^ (r & 7))) * 16), src);
        }
    };

    const int KT = Kdim / 32;
    issue(0, 0); cp_commit();

    for (int kt = 0; kt < KT; kt++) {
        // Single-sync pipeline: wait own groups, barrier (proves prev tile fully
        // consumed by all warps + this tile data visible), then prefetch next.
        cp_wait<0>();
        __syncthreads();
        if (kt + 1 < KT) { issue((kt + 1) * 32, (kt + 1) & 1); cp_commit(); }

        int cur = kt & 1;
        uint32_t ah_b = sbase + (uint32_t)(cur * STAGE);
        uint32_t al_b = ah_b + AH_BYTES;
        uint32_t bh_b = ah_b + 2 * AH_BYTES;
        uint32_t bl_b = bh_b + BH_BYTES;

        #pragma unroll
        for (int kc = 0; kc < 2; kc++) {
            uint32_t Af[2][2][4];
            #pragma unroll
            for (int rb = 0; rb < 2; rb++) {
                int rowa = wr * 32 + rb * 16 + (lane & 7) + ((lane >> 3) & 1) * 8;
                int cba = kc * 2 + (lane >> 4);
                ldsm4(Af[rb][0], ah_b + (uint32_t)((rowa * 5 + cba) * 16));
                ldsm4(Af[rb][1], al_b + (uint32_t)((rowa * 5 + cba) * 16));
            }
            #pragma unroll
            for (int dbp = 0; dbp < 4; dbp++) {
                int rowb = kc * 16 + ((lane >> 3) & 1) * 8 + (lane & 7);
                int cbb = wc * 8 + dbp * 2 + (lane >> 4);
                uint32_t bh[4], bl[4];
                ldsm4t(bh, tile_addr(bh_b, rowb, cbb, BCH));
                ldsm4t(bl, tile_addr(bl_b, rowb, cbb, BCH));
                // term-major: 4 independent accumulators between same-acc reuses
                #pragma unroll
                for (int rb = 0; rb < 2; rb++) {
                    mma_bf16(acc[rb][dbp * 2 + 0], Af[rb][0], bh);
                    mma_bf16(acc[rb][dbp * 2 + 1], Af[rb][0], bh + 2);
                }
                #pragma unroll
                for (int rb = 0; rb < 2; rb++) {
                    mma_bf16(acc[rb][dbp * 2 + 0], Af[rb][0], bl);
                    mma_bf16(acc[rb][dbp * 2 + 1], Af[rb][0], bl + 2);
                }
                #pragma unroll
                for (int rb = 0; rb < 2; rb++) {
                    mma_bf16(acc[rb][dbp * 2 + 0], Af[rb][1], bh);
                    mma_bf16(acc[rb][dbp * 2 + 1], Af[rb][1], bh + 2);
                }
            }
        }
    }

    // Epilogue
    #pragma unroll
    for (int rb = 0; rb < 2; rb++) {
        int row0 = bm0 + wr * 32 + rb * 16 + g;
        if (EPI == 0) {
            #pragma unroll
            for (int db = 0; db < 8; db++) {
                int c = bn0 + wc * 64 + db * 8 + 2 * t;
                float b0 = bias[c], b1 = bias[c + 1];
                float2 r;
                r.x = acc[rb][db][0] + b0; r.y = acc[rb][db][1] + b1;
                *(float2*)(Cf + (size_t)row0 * Ndim + c) = r;
                r.x = acc[rb][db][2] + b0; r.y = acc[rb][db][3] + b1;
                *(float2*)(Cf + (size_t)(row0 + 8) * Ndim + c) = r;
            }
        } else {
            int b0i = row0 / seq, s0 = row0 - b0i * seq;
            int b1i = (row0 + 8) / seq, s1 = (row0 + 8) - b1i * seq;
            #pragma unroll
            for (int db = 0; db < 8; db++) {
                int c = bn0 + wc * 64 + db * 8 + 2 * t;
                int h = c >> 6, d = c & 63;
                uint32_t hh, ll;
                size_t o0 = ((size_t)(b0i * H_ + h) * seq + s0) * 64 + d;
                split2(acc[rb][db][0] * scale, acc[rb][db][1] * scale, hh, ll);
                *(uint32_t*)(ohi + o0) = hh;
                *(uint32_t*)(olo + o0) = ll;
                size_t o1 = ((size_t)(b1i * H_ + h) * seq + s1) * 64 + d;
                split2(acc[rb][db][2] * scale, acc[rb][db][3] * scale, hh, ll);
                *(uint32_t*)(ohi + o1) = hh;
                *(uint32_t*)(olo + o1) = ll;
            }
        }
    }
}

// ---------------------------------------------------------------------------
// Flash attention: 128 queries/CTA, 8 warps, single-sync KV pipeline,
// 4-way MMA independence in QK and PV. Q pre-scaled 0.125*log2e -> exp2.
// ---------------------------------------------------------------------------
constexpr int FLASH_SMEM = (16384 + 32768) * 2;   // 96 KB

__global__ void __launch_bounds__(256, 2) flash_bf3(
    const bf16* __restrict__ Qhi_g, const bf16* __restrict__ Qlo_g,
    const bf16* __restrict__ Khi_g, const bf16* __restrict__ Klo_g,
    const bf16* __restrict__ Vhi_g, const bf16* __restrict__ Vlo_g,
    bf16* __restrict__ Ohi_g, bf16* __restrict__ Olo_g)
{
    extern __shared__ bf16 smem[];
    const int tid = threadIdx.x, w = tid >> 5, lane = tid & 31;
    const int n0 = blockIdx.x * 128, h = blockIdx.y, b = blockIdx.z;
    const int g = lane >> 2, t = lane & 3;
    const uint32_t sbase = smem_u32(smem);
    const uint32_t ql_b = sbase + 8192 * 2;

    const size_t qoff = ((size_t)(b * H_ + h) * N_ + n0) * 64;
    const size_t koff = ((size_t)(b * H_ + h) * M_) * 64;

    auto issueKV = [&](int kt, int stage) {
        uint32_t sb = sbase + (uint32_t)((16384 + stage * 16384) * 2);
        const bf16* srcs[4] = {Khi_g + koff, Klo_g + koff, Vhi_g + koff, Vlo_g + koff};
        #pragma unroll
        for (int j = 0; j < 8; j++) {
            int i = tid + j * 256;
            int arr = i >> 9, rem = i & 511, r = rem >> 3, cb = rem & 7;
            const bf16* src = srcs[arr] + (size_t)(kt * 64 + r) * 64 + cb * 8;
            uint32_t dst = sb + (uint32_t)(arr * 4096 * 2) +
                           (uint32_t)((r * 8 + (cb ^ (r & 7))) * 16);
            cp_async16(dst, src);
        }
    };

    issueKV(0, 0); cp_commit();

    for (int i = tid; i < 2048; i += 256) {
        int half = i >> 10, rem = i & 1023, r = rem >> 3, cb = rem & 7;
        const bf16* src = (half ? Qlo_g : Qhi_g) + qoff + (size_t)r * 64 + cb * 8;
        uint4 v = *(const uint4*)src;
        *(uint4*)(smem + (half ? 8192 : 0) + (r * 8 + (cb ^ (r & 7))) * 8) = v;
    }
    __syncthreads();

    const int rowa = w * 16 + (lane & 7) + ((lane >> 3) & 1) * 8;
    uint32_t qh[4][4];
    #pragma unroll
    for (int kc = 0; kc < 4; kc++)
        ldsm4(qh[kc], tile_addr(sbase, rowa, kc * 2 + (lane >> 4), 8));

    float m0 = -1e30f, m1 = -1e30f, l0 = 0.0f, l1 = 0.0f;
    float Oa[8][4];
    #pragma unroll
    for (int i = 0; i < 8; i++)
        #pragma unroll
        for (int j = 0; j < 4; j++) Oa[i][j] = 0.0f;

    for (int kt = 0; kt < M_ / 64; kt++) {
        // Single-sync pipeline
        cp_wait<0>();
        __syncthreads();
        if (kt + 1 < M_ / 64) { issueKV(kt + 1, (kt + 1) & 1); cp_commit(); }

        int cur = kt & 1;
        uint32_t kh_b = sbase + (uint32_t)((16384 + cur * 16384) * 2);
        uint32_t kl_b = kh_b + 4096 * 2;
        uint32_t vh_b = kh_b + 8192 * 2;
        uint32_t vl_b = kh_b + 12288 * 2;

        // S = Q @ K^T (bf16x3), log2-domain scores, 4-way independent accs
        float S[8][4];
        #pragma unroll
        for (int i = 0; i < 8; i++)
            #pragma unroll
            for (int j = 0; j < 4; j++) S[i][j] = 0.0f;

        const int rowk = ((lane >> 4)) * 8 + (lane & 7);
        const int cbk0 = (lane >> 3) & 1;
        #pragma unroll
        for (int kc = 0; kc < 4; kc++) {
            uint32_t ql[4];
            ldsm4(ql, tile_addr(ql_b, rowa, kc * 2 + (lane >> 4), 8));
            #pragma unroll
            for (int np = 0; np < 2; np++) {      // pairs of nbp
                uint32_t bh0[4], bl0[4], bh1[4], bl1[4];
                int rr0 = (np * 2 + 0) * 16 + rowk;
                int rr1 = (np * 2 + 1) * 16 + rowk;
                int cb = kc * 2 + cbk0;
                ldsm4(bh0, tile_addr(kh_b, rr0, cb, 8));
                ldsm4(bl0, tile_addr(kl_b, rr0, cb, 8));
                ldsm4(bh1, tile_addr(kh_b, rr1, cb, 8));
                ldsm4(bl1, tile_addr(kl_b, rr1, cb, 8));
                float* s0 = S[np * 4 + 0];
                float* s1 = S[np * 4 + 1];
                float* s2 = S[np * 4 + 2];
                float* s3 = S[np * 4 + 3];
                mma_bf16(s0, qh[kc], bh0);
                mma_bf16(s1, qh[kc], bh0 + 2);
                mma_bf16(s2, qh[kc], bh1);
                mma_bf16(s3, qh[kc], bh1 + 2);
                mma_bf16(s0, qh[kc], bl0);
                mma_bf16(s1, qh[kc], bl0 + 2);
                mma_bf16(s2, qh[kc], bl1);
                mma_bf16(s3, qh[kc], bl1 + 2);
                mma_bf16(s0, ql, bh0);
                mma_bf16(s1, ql, bh0 + 2);
                mma_bf16(s2, ql, bh1);
                mma_bf16(s3, ql, bh1 + 2);
            }
        }

        // Online softmax in exp2 domain
        float vx0 = -1e30f, vx1 = -1e30f;
        #pragma unroll
        for (int nb = 0; nb < 8; nb++) {
            vx0 = fmaxf(vx0, fmaxf(S[nb][0], S[nb][1]));
            vx1 = fmaxf(vx1, fmaxf(S[nb][2], S[nb][3]));
        }
        vx0 = fmaxf(vx0, __shfl_xor_sync(0xffffffffu, vx0, 1, 4));
        vx0 = fmaxf(vx0, __shfl_xor_sync(0xffffffffu, vx0, 2, 4));
        vx1 = fmaxf(vx1, __shfl_xor_sync(0xffffffffu, vx1, 1, 4));
        vx1 = fmaxf(vx1, __shfl_xor_sync(0xffffffffu, vx1, 2, 4));
        float mn0 = fmaxf(m0, vx0), mn1 = fmaxf(m1, vx1);
        float a0 = ex2(m0 - mn0), a1 = ex2(m1 - mn1);
        float rs0 = 0.0f, rs1 = 0.0f;
        #pragma unroll
        for (int nb = 0; nb < 8; nb++) {
            S[nb][0] = ex2(S[nb][0] - mn0);
            S[nb][1] = ex2(S[nb][1] - mn0);
            S[nb][2] = ex2(S[nb][2] - mn1);
            S[nb][3] = ex2(S[nb][3] - mn1);
            rs0 += S[nb][0] + S[nb][1];
            rs1 += S[nb][2] + S[nb][3];
        }
        rs0 += __shfl_xor_sync(0xffffffffu, rs0, 1, 4);
        rs0 += __shfl_xor_sync(0xffffffffu, rs0, 2, 4);
        rs1 += __shfl_xor_sync(0xffffffffu, rs1, 1, 4);
        rs1 += __shfl_xor_sync(0xffffffffu, rs1, 2, 4);
        l0 = l0 * a0 + rs0; l1 = l1 * a1 + rs1;
        m0 = mn0; m1 = mn1;
        #pragma unroll
        for (int db = 0; db < 8; db++) {
            Oa[db][0] *= a0; Oa[db][1] *= a0;
            Oa[db][2] *= a1; Oa[db][3] *= a1;
        }

        // O += P @ V, 4-way independent accs
        #pragma unroll
        for (int kc = 0; kc < 4; kc++) {
            uint32_t ah[4], al[4];
            split2(S[2*kc  ][0], S[2*kc  ][1], ah[0], al[0]);
            split2(S[2*kc  ][2], S[2*kc  ][3], ah[1], al[1]);
            split2(S[2*kc+1][0], S[2*kc+1][1], ah[2], al[2]);
            split2(S[2*kc+1][2], S[2*kc+1][3], ah[3], al[3]);
            int rowv = kc * 16 + ((lane >> 3) & 1) * 8 + (lane & 7);
            #pragma unroll
            for (int dp = 0; dp < 2; dp++) {      // pairs of dbp
                uint32_t vh0[4], vl0[4], vh1[4], vl1[4];
                int cb0 = (dp * 2 + 0) * 2 + (lane >> 4);
                int cb1 = (dp * 2 + 1) * 2 + (lane >> 4);
                ldsm4t(vh0, tile_addr(vh_b, rowv, cb0, 8));
                ldsm4t(vl0, tile_addr(vl_b, rowv, cb0, 8));
                ldsm4t(vh1, tile_addr(vh_b, rowv, cb1, 8));
                ldsm4t(vl1, tile_addr(vl_b, rowv, cb1, 8));
                float* o0 = Oa[dp * 4 + 0];
                float* o1 = Oa[dp * 4 + 1];
                float* o2 = Oa[dp * 4 + 2];
                float* o3 = Oa[dp * 4 + 3];
                mma_bf16(o0, ah, vh0);
                mma_bf16(o1, ah, vh0 + 2);
                mma_bf16(o2, ah, vh1);
                mma_bf16(o3, ah, vh1 + 2);
                mma_bf16(o0, ah, vl0);
                mma_bf16(o1, ah, vl0 + 2);
                mma_bf16(o2, ah, vl1);
                mma_bf16(o3, ah, vl1 + 2);
                mma_bf16(o0, al, vh0);
                mma_bf16(o1, al, vh0 + 2);
                mma_bf16(o2, al, vh1);
                mma_bf16(o3, al, vh1 + 2);
            }
        }
    }

    float i0 = 1.0f / l0, i1 = 1.0f / l1;
    int rq = w * 16 + g;
    #pragma unroll
    for (int db = 0; db < 8; db++) {
        int c = h * 64 + db * 8 + 2 * t;
        uint32_t hh, ll;
        size_t o0 = (size_t)(b * N_ + n0 + rq) * 512 + c;
        split2(Oa[db][0] * i0, Oa[db][1] * i0, hh, ll);
        *(uint32_t*)(g_ohi + o0) = hh;
        *(uint32_t*)(g_olo + o0) = ll;
        size_t o1 = (size_t)(b * N_ + n0 + rq + 8) * 512 + c;
        split2(Oa[db][2] * i1, Oa[db][3] * i1, hh, ll);
        *(uint32_t*)(g_ohi + o1) = hh;
        *(uint32_t*)(g_olo + o1) = ll;
    }
}

// ---------------------------------------------------------------------------
// Launch
// ---------------------------------------------------------------------------
extern "C" void kernel_launch(void* const* d_in, const int* in_sizes, int n_in,
                              void* d_out, int out_size)
{
    const float* x   = (const float*)d_in[0];
    const float* ctx = (const float*)d_in[1];
    const float* Wq  = (const float*)d_in[2];
    const float* Wk  = (const float*)d_in[3];
    const float* Wv  = (const float*)d_in[4];
    const float* Wo  = (const float*)d_in[5];
    const float* bo  = (const float*)d_in[6];
    float* out = (float*)d_out;

    #define SYM(p, s) void* p; cudaGetSymbolAddress(&p, s);
    SYM(xhi, g_xhi) SYM(xlo, g_xlo) SYM(chi, g_chi) SYM(clo, g_clo)
    SYM(wqhi, g_wqhi) SYM(wqlo, g_wqlo) SYM(wkhi, g_wkhi) SYM(wklo, g_wklo)
    SYM(wvhi, g_wvhi) SYM(wvlo, g_wvlo) SYM(wohi, g_wohi) SYM(wolo, g_wolo)
    SYM(qhi, g_qhi) SYM(qlo, g_qlo) SYM(khi, g_khi) SYM(klo, g_klo)
    SYM(vhi, g_vhi) SYM(vlo, g_vlo) SYM(ohi, g_ohi) SYM(olo, g_olo)
    #undef SYM

    constexpr int GEMM_SMEM_A = 2 * (2 * 64 * 5 * 16 + 2 * 32 * 16 * 16);   // 53248
    constexpr int GEMM_SMEM_B = 2 * (2 * 128 * 5 * 16 + 2 * 32 * 8 * 16);   // 57344
    cudaFuncSetAttribute(gemm_bf3<64, 128, 1>,
                         cudaFuncAttributeMaxDynamicSharedMemorySize, GEMM_SMEM_A);
    cudaFuncSetAttribute(gemm_bf3<128, 64, 0>,
                         cudaFuncAttributeMaxDynamicSharedMemorySize, GEMM_SMEM_B);
    cudaFuncSetAttribute(flash_bf3,
                         cudaFuncAttributeMaxDynamicSharedMemorySize, FLASH_SMEM);

    split_inputs <<<dim3((16384 * 320 / 4 + 255) / 256, 2), 256>>>(
        (const float4*)x, (const float4*)ctx);
    split_weights<<<dim3((768 * 512 / 4 + 255) / 256, 4), 256>>>(
        (const float4*)Wq, (const float4*)Wk, (const float4*)Wv, (const float4*)Wo);

    // q-projection (scale = 0.125*log2e folded once here)
    gemm_bf3<64, 128, 1><<<dim3(4, 256, 1), 128, GEMM_SMEM_A>>>(
        (const bf16*)xhi, (const bf16*)xlo, (const bf16*)wqhi, (const bf16*)wqlo,
        nullptr, nullptr, nullptr, nullptr, (bf16*)qhi, (bf16*)qlo,
        nullptr, nullptr, 512, 320, N_, QSCALE_);
    // k- and v-projections merged into one launch (z selects weight/output set)
    gemm_bf3<64, 128, 1><<<dim3(4, 64, 2), 128, GEMM_SMEM_A>>>(
        (const bf16*)chi, (const bf16*)clo, (const bf16*)wkhi, (const bf16*)wklo,
        (const bf16*)wvhi, (const bf16*)wvlo, nullptr, nullptr,
        (bf16*)khi, (bf16*)klo, (bf16*)vhi, (bf16*)vlo, 512, 768, M_, 1.0f);

    // Attention
    flash_bf3<<<dim3(N_ / 128, H_, B_), 256, FLASH_SMEM>>>(
        (const bf16*)qhi, (const bf16*)qlo, (const bf16*)khi, (const bf16*)klo,
        (const bf16*)vhi, (const bf16*)vlo, (bf16*)ohi, (bf16*)olo);

    // Output projection
    gemm_bf3<128, 64, 0><<<dim3(5, 128, 1), 128, GEMM_SMEM_B>>>(
        (const bf16*)ohi, (const bf16*)olo, (const bf16*)wohi, (const bf16*)wolo,
        nullptr, nullptr, bo, out, nullptr, nullptr,
        nullptr, nullptr, 320, 512, 0, 1.0f);
}

// round 12
// speedup vs baseline: 1.0509x; 1.0509x over previous
#include <cuda_runtime.h>
#include <cuda_bf16.h>
#include <cstdint>

using bf16 = __nv_bfloat16;

constexpr int B_  = 4;
constexpr int N_  = 4096;
constexpr int M_  = 1024;
constexpr int QD_ = 320;
constexpr int CD_ = 768;
constexpr int ID_ = 512;
constexpr int H_  = 8;
// softmax scale with log2(e) folded: scores land in log2 domain, softmax via exp2
constexpr float QSCALE_ = 0.125f * 1.4426950408889634f;

// ---------------------------------------------------------------------------
// Device-global scratch (hi/lo bf16 pairs)
// ---------------------------------------------------------------------------
__device__ bf16 g_xhi[16384 * 320], g_xlo[16384 * 320];
__device__ bf16 g_chi[4096 * 768],  g_clo[4096 * 768];
__device__ bf16 g_wqhi[320 * 512],  g_wqlo[320 * 512];
__device__ bf16 g_wkhi[768 * 512],  g_wklo[768 * 512];
__device__ bf16 g_wvhi[768 * 512],  g_wvlo[768 * 512];
__device__ bf16 g_wohi[512 * 320],  g_wolo[512 * 320];
__device__ bf16 g_qhi[16384 * 512], g_qlo[16384 * 512];  // head-major [b,h,n,64]
__device__ bf16 g_khi[4096 * 512],  g_klo[4096 * 512];   // head-major [b,h,m,64]
__device__ bf16 g_vhi[4096 * 512],  g_vlo[4096 * 512];
__device__ bf16 g_ohi[16384 * 512], g_olo[16384 * 512];  // row-major [b*n, 512]

// ---------------------------------------------------------------------------
// Helpers
// ---------------------------------------------------------------------------
__device__ __forceinline__ uint32_t smem_u32(const void* p) {
    return (uint32_t)__cvta_generic_to_shared(p);
}
__device__ __forceinline__ uint32_t pk2(bf16 lo, bf16 hi) {
    return ((uint32_t)__bfloat16_as_ushort(hi) << 16) |
            (uint32_t)__bfloat16_as_ushort(lo);
}
__device__ __forceinline__ void split2(float x, float y, uint32_t& h, uint32_t& l) {
    bf16 xh = __float2bfloat16_rn(x), yh = __float2bfloat16_rn(y);
    h = pk2(xh, yh);
    l = pk2(__float2bfloat16_rn(x - __bfloat162float(xh)),
            __float2bfloat16_rn(y - __bfloat162float(yh)));
}
__device__ __forceinline__ float ex2(float x) {
    float y;
    asm("ex2.approx.ftz.f32 %0, %1;" : "=f"(y) : "f"(x));
    return y;
}
__device__ __forceinline__ void mma_bf16(float* d, const uint32_t* a, const uint32_t* b) {
    asm volatile(
        "mma.sync.aligned.m16n8k16.row.col.f32.bf16.bf16.f32 "
        "{%0,%1,%2,%3}, {%4,%5,%6,%7}, {%8,%9}, {%0,%1,%2,%3};\n"
        : "+f"(d[0]), "+f"(d[1]), "+f"(d[2]), "+f"(d[3])
        : "r"(a[0]), "r"(a[1]), "r"(a[2]), "r"(a[3]), "r"(b[0]), "r"(b[1]));
}
__device__ __forceinline__ void ldsm4(uint32_t* r, uint32_t a) {
    asm volatile("ldmatrix.sync.aligned.m8n8.x4.shared.b16 {%0,%1,%2,%3}, [%4];\n"
        : "=r"(r[0]), "=r"(r[1]), "=r"(r[2]), "=r"(r[3]) : "r"(a));
}
__device__ __forceinline__ void ldsm4t(uint32_t* r, uint32_t a) {
    asm volatile("ldmatrix.sync.aligned.m8n8.x4.trans.shared.b16 {%0,%1,%2,%3}, [%4];\n"
        : "=r"(r[0]), "=r"(r[1]), "=r"(r[2]), "=r"(r[3]) : "r"(a));
}
__device__ __forceinline__ uint32_t tile_addr(uint32_t base, int row, int cb, int cpr) {
    return base + (uint32_t)((row * cpr + (cb ^ (row & 7))) * 16);
}
__device__ __forceinline__ void cp_async16(uint32_t dst, const void* src) {
    asm volatile("cp.async.ca.shared.global [%0], [%1], 16;\n" :: "r"(dst), "l"(src));
}
__device__ __forceinline__ void cp_commit() {
    asm volatile("cp.async.commit_group;\n");
}
template<int NW> __device__ __forceinline__ void cp_wait() {
    asm volatile("cp.async.wait_group %0;\n" :: "n"(NW));
}

// ---------------------------------------------------------------------------
// Merged split kernels (2 launches total)
// ---------------------------------------------------------------------------
__device__ __forceinline__ void split4(const float4* src, uint2* hi, uint2* lo, int i) {
    float4 v = src[i];
    uint32_t h0, l0, h1, l1;
    split2(v.x, v.y, h0, l0);
    split2(v.z, v.w, h1, l1);
    hi[i] = make_uint2(h0, h1);
    lo[i] = make_uint2(l0, l1);
}
__global__ void split_inputs(const float4* __restrict__ x, const float4* __restrict__ c)
{
    int i = blockIdx.x * blockDim.x + threadIdx.x;
    if (blockIdx.y == 0) {
        if (i < 16384 * 320 / 4) split4(x, (uint2*)g_xhi, (uint2*)g_xlo, i);
    } else {
        if (i < 4096 * 768 / 4)  split4(c, (uint2*)g_chi, (uint2*)g_clo, i);
    }
}
__global__ void split_weights(const float4* __restrict__ wq, const float4* __restrict__ wk,
                              const float4* __restrict__ wv, const float4* __restrict__ wo)
{
    int i = blockIdx.x * blockDim.x + threadIdx.x;
    switch (blockIdx.y) {
    case 0: if (i < 320 * 512 / 4) split4(wq, (uint2*)g_wqhi, (uint2*)g_wqlo, i); break;
    case 1: if (i < 768 * 512 / 4) split4(wk, (uint2*)g_wkhi, (uint2*)g_wklo, i); break;
    case 2: if (i < 768 * 512 / 4) split4(wv, (uint2*)g_wvhi, (uint2*)g_wvlo, i); break;
    default: if (i < 512 * 320 / 4) split4(wo, (uint2*)g_wohi, (uint2*)g_wolo, i); break;
    }
}

// ---------------------------------------------------------------------------
// bf16x3 GEMM, BK=32, single-sync double-buffered pipeline,
// STRENGTH-REDUCED loader: all cp.async addresses affine in slot/tile index,
// per-tile advance = one pointer add. No div/mod/XOR in the hot loop.
// ---------------------------------------------------------------------------
template<int BM, int BN, int EPI>
__global__ void __launch_bounds__(128, 4) gemm_bf3(
    const bf16* __restrict__ Ahi, const bf16* __restrict__ Alo,
    const bf16* __restrict__ Bhi, const bf16* __restrict__ Blo,
    const bf16* __restrict__ Bhi2, const bf16* __restrict__ Blo2,
    const float* __restrict__ bias, float* __restrict__ Cf,
    bf16* __restrict__ Ohi, bf16* __restrict__ Olo,
    bf16* __restrict__ Ohi2, bf16* __restrict__ Olo2,
    int Ndim, int Kdim, int seq, float scale)
{
    constexpr int WR = BM / 32, WC = BN / 64, NT = WR * WC * 32;
    constexpr int BCH = BN / 8;
    constexpr int AH_BYTES = BM * 5 * 16;
    constexpr int BH_BYTES = 32 * BCH * 16;
    constexpr int STAGE = 2 * AH_BYTES + 2 * BH_BYTES;
    constexpr int SA = BM * 4 / NT;        // A slots per half (r advances 32/slot)
    constexpr int SB = 32 * BCH / NT;      // B slots per half (r advances NT/BCH)
    constexpr int BRADV = NT / BCH;        // B row advance per slot

    extern __shared__ char smc[];
    const uint32_t sbase = smem_u32(smc);
    const int tid = threadIdx.x, w = tid >> 5, lane = tid & 31;
    const int wr = w % WR, wc = w / WR;
    const int bm0 = blockIdx.y * BM, bn0 = blockIdx.x * BN;
    const int g = lane >> 2, t = lane & 3;

    const bf16* bhi = (blockIdx.z == 0) ? Bhi : Bhi2;
    const bf16* blo = (blockIdx.z == 0) ? Blo : Blo2;
    bf16* ohi = (blockIdx.z == 0) ? Ohi : Ohi2;
    bf16* olo = (blockIdx.z == 0) ? Olo : Olo2;

    // --- loader bases (computed ONCE) ---
    const int r0a = tid >> 2, cb0a = tid & 3;
    const bf16* aph = Ahi + (size_t)(bm0 + r0a) * Kdim + cb0a * 8;
    const bf16* apl = Alo + (size_t)(bm0 + r0a) * Kdim + cb0a * 8;
    const uint32_t adst0 = (uint32_t)((r0a * 5 + cb0a) * 16);
    const size_t aSlot = (size_t)32 * Kdim;            // A slot stride (elements)

    const int r0b = tid / BCH, cb0b = tid % BCH;
    const bf16* bph = bhi + (size_t)r0b * Ndim + bn0 + cb0b * 8;
    const bf16* bpl = blo + (size_t)r0b * Ndim + bn0 + cb0b * 8;
    const uint32_t bdst0 = (uint32_t)((r0b * BCH + (cb0b ^ (r0b & 7))) * 16);
    const size_t bSlot = (size_t)BRADV * Ndim;         // B slot stride (elements)
    const size_t bTile = (size_t)32 * Ndim;            // B per-tile advance

    float acc[2][8][4];
    #pragma unroll
    for (int a = 0; a < 2; a++)
        #pragma unroll
        for (int i = 0; i < 8; i++)
            #pragma unroll
            for (int j = 0; j < 4; j++) acc[a][i][j] = 0.0f;

    auto issue = [&](int stage) {
        uint32_t sb = sbase + (uint32_t)(stage * STAGE);
        #pragma unroll
        for (int s = 0; s < SA; s++) {
            cp_async16(sb + adst0 + s * 2560, aph + s * aSlot);
            cp_async16(sb + AH_BYTES + adst0 + s * 2560, apl + s * aSlot);
        }
        #pragma unroll
        for (int s = 0; s < SB; s++) {
            cp_async16(sb + 2 * AH_BYTES + bdst0 + s * (BRADV * BCH * 16),
                       bph + s * bSlot);
            cp_async16(sb + 2 * AH_BYTES + BH_BYTES + bdst0 + s * (BRADV * BCH * 16),
                       bpl + s * bSlot);
        }
        aph += 32; apl += 32;           // next k-tile: 32 columns
        bph += bTile; bpl += bTile;     // next k-tile: 32 rows
    };

    const int KT = Kdim / 32;
    issue(0); cp_commit();

    for (int kt = 0; kt < KT; kt++) {
        cp_wait<0>();
        __syncthreads();
        if (kt + 1 < KT) { issue((kt + 1) & 1); cp_commit(); }

        int cur = kt & 1;
        uint32_t ah_b = sbase + (uint32_t)(cur * STAGE);
        uint32_t al_b = ah_b + AH_BYTES;
        uint32_t bh_b = ah_b + 2 * AH_BYTES;
        uint32_t bl_b = bh_b + BH_BYTES;

        #pragma unroll
        for (int kc = 0; kc < 2; kc++) {
            uint32_t Af[2][2][4];
            #pragma unroll
            for (int rb = 0; rb < 2; rb++) {
                int rowa = wr * 32 + rb * 16 + (lane & 7) + ((lane >> 3) & 1) * 8;
                int cba = kc * 2 + (lane >> 4);
                ldsm4(Af[rb][0], ah_b + (uint32_t)((rowa * 5 + cba) * 16));
                ldsm4(Af[rb][1], al_b + (uint32_t)((rowa * 5 + cba) * 16));
            }
            #pragma unroll
            for (int dbp = 0; dbp < 4; dbp++) {
                int rowb = kc * 16 + ((lane >> 3) & 1) * 8 + (lane & 7);
                int cbb = wc * 8 + dbp * 2 + (lane >> 4);
                uint32_t bh[4], bl[4];
                ldsm4t(bh, tile_addr(bh_b, rowb, cbb, BCH));
                ldsm4t(bl, tile_addr(bl_b, rowb, cbb, BCH));
                #pragma unroll
                for (int rb = 0; rb < 2; rb++) {
                    mma_bf16(acc[rb][dbp * 2 + 0], Af[rb][0], bh);
                    mma_bf16(acc[rb][dbp * 2 + 1], Af[rb][0], bh + 2);
                }
                #pragma unroll
                for (int rb = 0; rb < 2; rb++) {
                    mma_bf16(acc[rb][dbp * 2 + 0], Af[rb][0], bl);
                    mma_bf16(acc[rb][dbp * 2 + 1], Af[rb][0], bl + 2);
                }
                #pragma unroll
                for (int rb = 0; rb < 2; rb++) {
                    mma_bf16(acc[rb][dbp * 2 + 0], Af[rb][1], bh);
                    mma_bf16(acc[rb][dbp * 2 + 1], Af[rb][1], bh + 2);
                }
            }
        }
    }

    // Epilogue
    #pragma unroll
    for (int rb = 0; rb < 2; rb++) {
        int row0 = bm0 + wr * 32 + rb * 16 + g;
        if (EPI == 0) {
            #pragma unroll
            for (int db = 0; db < 8; db++) {
                int c = bn0 + wc * 64 + db * 8 + 2 * t;
                float b0 = bias[c], b1 = bias[c + 1];
                float2 r;
                r.x = acc[rb][db][0] + b0; r.y = acc[rb][db][1] + b1;
                *(float2*)(Cf + (size_t)row0 * Ndim + c) = r;
                r.x = acc[rb][db][2] + b0; r.y = acc[rb][db][3] + b1;
                *(float2*)(Cf + (size_t)(row0 + 8) * Ndim + c) = r;
            }
        } else {
            int b0i = row0 / seq, s0 = row0 - b0i * seq;
            int b1i = (row0 + 8) / seq, s1 = (row0 + 8) - b1i * seq;
            #pragma unroll
            for (int db = 0; db < 8; db++) {
                int c = bn0 + wc * 64 + db * 8 + 2 * t;
                int h = c >> 6, d = c & 63;
                uint32_t hh, ll;
                size_t o0 = ((size_t)(b0i * H_ + h) * seq + s0) * 64 + d;
                split2(acc[rb][db][0] * scale, acc[rb][db][1] * scale, hh, ll);
                *(uint32_t*)(ohi + o0) = hh;
                *(uint32_t*)(olo + o0) = ll;
                size_t o1 = ((size_t)(b1i * H_ + h) * seq + s1) * 64 + d;
                split2(acc[rb][db][2] * scale, acc[rb][db][3] * scale, hh, ll);
                *(uint32_t*)(ohi + o1) = hh;
                *(uint32_t*)(olo + o1) = ll;
            }
        }
    }
}

// ---------------------------------------------------------------------------
// Flash attention: 128 queries/CTA, 8 warps, single-sync KV pipeline with
// STRENGTH-REDUCED loader, 4-way MMA independence. Q pre-scaled -> exp2.
// ---------------------------------------------------------------------------
constexpr int FLASH_SMEM = (16384 + 32768) * 2;   // 96 KB

__global__ void __launch_bounds__(256, 2) flash_bf3(
    const bf16* __restrict__ Qhi_g, const bf16* __restrict__ Qlo_g,
    const bf16* __restrict__ Khi_g, const bf16* __restrict__ Klo_g,
    const bf16* __restrict__ Vhi_g, const bf16* __restrict__ Vlo_g,
    bf16* __restrict__ Ohi_g, bf16* __restrict__ Olo_g)
{
    extern __shared__ bf16 smem[];
    const int tid = threadIdx.x, w = tid >> 5, lane = tid & 31;
    const int n0 = blockIdx.x * 128, h = blockIdx.y, b = blockIdx.z;
    const int g = lane >> 2, t = lane & 3;
    const uint32_t sbase = smem_u32(smem);
    const uint32_t ql_b = sbase + 8192 * 2;

    const size_t qoff = ((size_t)(b * H_ + h) * N_ + n0) * 64;
    const size_t koff = ((size_t)(b * H_ + h) * M_) * 64;

    // --- KV loader bases (computed ONCE); slot parity -> 2 fixed dst offsets ---
    const int r0 = tid >> 3, cb0 = tid & 7;              // r0 in [0,32)
    const uint32_t d0 = (uint32_t)((r0 * 8 + (cb0 ^ (r0 & 7))) * 16);
    const uint32_t d1 = (uint32_t)(((r0 + 32) * 8 + (cb0 ^ (r0 & 7))) * 16);
    const size_t poff = (size_t)r0 * 64 + cb0 * 8;
    const bf16* pkh = Khi_g + koff + poff;
    const bf16* pkl = Klo_g + koff + poff;
    const bf16* pvh = Vhi_g + koff + poff;
    const bf16* pvl = Vlo_g + koff + poff;

    auto issueKV = [&](int stage) {
        uint32_t sb = sbase + (uint32_t)((16384 + stage * 16384) * 2);
        cp_async16(sb +     0 + d0, pkh);
        cp_async16(sb +     0 + d1, pkh + 2048);
        cp_async16(sb +  8192 + d0, pkl);
        cp_async16(sb +  8192 + d1, pkl + 2048);
        cp_async16(sb + 16384 + d0, pvh);
        cp_async16(sb + 16384 + d1, pvh + 2048);
        cp_async16(sb + 24576 + d0, pvl);
        cp_async16(sb + 24576 + d1, pvl + 2048);
        pkh += 4096; pkl += 4096; pvh += 4096; pvl += 4096;   // next 64-key tile
    };

    issueKV(0); cp_commit();

    for (int i = tid; i < 2048; i += 256) {
        int half = i >> 10, rem = i & 1023, r = rem >> 3, cb = rem & 7;
        const bf16* src = (half ? Qlo_g : Qhi_g) + qoff + (size_t)r * 64 + cb * 8;
        uint4 v = *(const uint4*)src;
        *(uint4*)(smem + (half ? 8192 : 0) + (r * 8 + (cb ^ (r & 7))) * 8) = v;
    }
    __syncthreads();

    const int rowa = w * 16 + (lane & 7) + ((lane >> 3) & 1) * 8;
    uint32_t qh[4][4];
    #pragma unroll
    for (int kc = 0; kc < 4; kc++)
        ldsm4(qh[kc], tile_addr(sbase, rowa, kc * 2 + (lane >> 4), 8));

    float m0 = -1e30f, m1 = -1e30f, l0 = 0.0f, l1 = 0.0f;
    float Oa[8][4];
    #pragma unroll
    for (int i = 0; i < 8; i++)
        #pragma unroll
        for (int j = 0; j < 4; j++) Oa[i][j] = 0.0f;

    for (int kt = 0; kt < M_ / 64; kt++) {
        cp_wait<0>();
        __syncthreads();
        if (kt + 1 < M_ / 64) { issueKV((kt + 1) & 1); cp_commit(); }

        int cur = kt & 1;
        uint32_t kh_b = sbase + (uint32_t)((16384 + cur * 16384) * 2);
        uint32_t kl_b = kh_b + 4096 * 2;
        uint32_t vh_b = kh_b + 8192 * 2;
        uint32_t vl_b = kh_b + 12288 * 2;

        // S = Q @ K^T (bf16x3), log2-domain scores, 4-way independent accs
        float S[8][4];
        #pragma unroll
        for (int i = 0; i < 8; i++)
            #pragma unroll
            for (int j = 0; j < 4; j++) S[i][j] = 0.0f;

        const int rowk = ((lane >> 4)) * 8 + (lane & 7);
        const int cbk0 = (lane >> 3) & 1;
        #pragma unroll
        for (int kc = 0; kc < 4; kc++) {
            uint32_t ql[4];
            ldsm4(ql, tile_addr(ql_b, rowa, kc * 2 + (lane >> 4), 8));
            #pragma unroll
            for (int np = 0; np < 2; np++) {
                uint32_t bh0[4], bl0[4], bh1[4], bl1[4];
                int rr0 = (np * 2 + 0) * 16 + rowk;
                int rr1 = (np * 2 + 1) * 16 + rowk;
                int cb = kc * 2 + cbk0;
                ldsm4(bh0, tile_addr(kh_b, rr0, cb, 8));
                ldsm4(bl0, tile_addr(kl_b, rr0, cb, 8));
                ldsm4(bh1, tile_addr(kh_b, rr1, cb, 8));
                ldsm4(bl1, tile_addr(kl_b, rr1, cb, 8));
                float* s0 = S[np * 4 + 0];
                float* s1 = S[np * 4 + 1];
                float* s2 = S[np * 4 + 2];
                float* s3 = S[np * 4 + 3];
                mma_bf16(s0, qh[kc], bh0);
                mma_bf16(s1, qh[kc], bh0 + 2);
                mma_bf16(s2, qh[kc], bh1);
                mma_bf16(s3, qh[kc], bh1 + 2);
                mma_bf16(s0, qh[kc], bl0);
                mma_bf16(s1, qh[kc], bl0 + 2);
                mma_bf16(s2, qh[kc], bl1);
                mma_bf16(s3, qh[kc], bl1 + 2);
                mma_bf16(s0, ql, bh0);
                mma_bf16(s1, ql, bh0 + 2);
                mma_bf16(s2, ql, bh1);
                mma_bf16(s3, ql, bh1 + 2);
            }
        }

        // Online softmax in exp2 domain
        float vx0 = -1e30f, vx1 = -1e30f;
        #pragma unroll
        for (int nb = 0; nb < 8; nb++) {
            vx0 = fmaxf(vx0, fmaxf(S[nb][0], S[nb][1]));
            vx1 = fmaxf(vx1, fmaxf(S[nb][2], S[nb][3]));
        }
        vx0 = fmaxf(vx0, __shfl_xor_sync(0xffffffffu, vx0, 1, 4));
        vx0 = fmaxf(vx0, __shfl_xor_sync(0xffffffffu, vx0, 2, 4));
        vx1 = fmaxf(vx1, __shfl_xor_sync(0xffffffffu, vx1, 1, 4));
        vx1 = fmaxf(vx1, __shfl_xor_sync(0xffffffffu, vx1, 2, 4));
        float mn0 = fmaxf(m0, vx0), mn1 = fmaxf(m1, vx1);
        float a0 = ex2(m0 - mn0), a1 = ex2(m1 - mn1);
        float rs0 = 0.0f, rs1 = 0.0f;
        #pragma unroll
        for (int nb = 0; nb < 8; nb++) {
            S[nb][0] = ex2(S[nb][0] - mn0);
            S[nb][1] = ex2(S[nb][1] - mn0);
            S[nb][2] = ex2(S[nb][2] - mn1);
            S[nb][3] = ex2(S[nb][3] - mn1);
            rs0 += S[nb][0] + S[nb][1];
            rs1 += S[nb][2] + S[nb][3];
        }
        rs0 += __shfl_xor_sync(0xffffffffu, rs0, 1, 4);
        rs0 += __shfl_xor_sync(0xffffffffu, rs0, 2, 4);
        rs1 += __shfl_xor_sync(0xffffffffu, rs1, 1, 4);
        rs1 += __shfl_xor_sync(0xffffffffu, rs1, 2, 4);
        l0 = l0 * a0 + rs0; l1 = l1 * a1 + rs1;
        m0 = mn0; m1 = mn1;
        #pragma unroll
        for (int db = 0; db < 8; db++) {
            Oa[db][0] *= a0; Oa[db][1] *= a0;
            Oa[db][2] *= a1; Oa[db][3] *= a1;
        }

        // O += P @ V, 4-way independent accs
        #pragma unroll
        for (int kc = 0; kc < 4; kc++) {
            uint32_t ah[4], al[4];
            split2(S[2*kc  ][0], S[2*kc  ][1], ah[0], al[0]);
            split2(S[2*kc  ][2], S[2*kc  ][3], ah[1], al[1]);
            split2(S[2*kc+1][0], S[2*kc+1][1], ah[2], al[2]);
            split2(S[2*kc+1][2], S[2*kc+1][3], ah[3], al[3]);
            int rowv = kc * 16 + ((lane >> 3) & 1) * 8 + (lane & 7);
            #pragma unroll
            for (int dp = 0; dp < 2; dp++) {
                uint32_t vh0[4], vl0[4], vh1[4], vl1[4];
                int cb0v = (dp * 2 + 0) * 2 + (lane >> 4);
                int cb1v = (dp * 2 + 1) * 2 + (lane >> 4);
                ldsm4t(vh0, tile_addr(vh_b, rowv, cb0v, 8));
                ldsm4t(vl0, tile_addr(vl_b, rowv, cb0v, 8));
                ldsm4t(vh1, tile_addr(vh_b, rowv, cb1v, 8));
                ldsm4t(vl1, tile_addr(vl_b, rowv, cb1v, 8));
                float* o0 = Oa[dp * 4 + 0];
                float* o1 = Oa[dp * 4 + 1];
                float* o2 = Oa[dp * 4 + 2];
                float* o3 = Oa[dp * 4 + 3];
                mma_bf16(o0, ah, vh0);
                mma_bf16(o1, ah, vh0 + 2);
                mma_bf16(o2, ah, vh1);
                mma_bf16(o3, ah, vh1 + 2);
                mma_bf16(o0, ah, vl0);
                mma_bf16(o1, ah, vl0 + 2);
                mma_bf16(o2, ah, vl1);
                mma_bf16(o3, ah, vl1 + 2);
                mma_bf16(o0, al, vh0);
                mma_bf16(o1, al, vh0 + 2);
                mma_bf16(o2, al, vh1);
                mma_bf16(o3, al, vh1 + 2);
            }
        }
    }

    float i0 = 1.0f / l0, i1 = 1.0f / l1;
    int rq = w * 16 + g;
    #pragma unroll
    for (int db = 0; db < 8; db++) {
        int c = h * 64 + db * 8 + 2 * t;
        uint32_t hh, ll;
        size_t o0 = (size_t)(b * N_ + n0 + rq) * 512 + c;
        split2(Oa[db][0] * i0, Oa[db][1] * i0, hh, ll);
        *(uint32_t*)(g_ohi + o0) = hh;
        *(uint32_t*)(g_olo + o0) = ll;
        size_t o1 = (size_t)(b * N_ + n0 + rq + 8) * 512 + c;
        split2(Oa[db][2] * i1, Oa[db][3] * i1, hh, ll);
        *(uint32_t*)(g_ohi + o1) = hh;
        *(uint32_t*)(g_olo + o1) = ll;
    }
}

// ---------------------------------------------------------------------------
// Launch
// ---------------------------------------------------------------------------
extern "C" void kernel_launch(void* const* d_in, const int* in_sizes, int n_in,
                              void* d_out, int out_size)
{
    const float* x   = (const float*)d_in[0];
    const float* ctx = (const float*)d_in[1];
    const float* Wq  = (const float*)d_in[2];
    const float* Wk  = (const float*)d_in[3];
    const float* Wv  = (const float*)d_in[4];
    const float* Wo  = (const float*)d_in[5];
    const float* bo  = (const float*)d_in[6];
    float* out = (float*)d_out;

    #define SYM(p, s) void* p; cudaGetSymbolAddress(&p, s);
    SYM(xhi, g_xhi) SYM(xlo, g_xlo) SYM(chi, g_chi) SYM(clo, g_clo)
    SYM(wqhi, g_wqhi) SYM(wqlo, g_wqlo) SYM(wkhi, g_wkhi) SYM(wklo, g_wklo)
    SYM(wvhi, g_wvhi) SYM(wvlo, g_wvlo) SYM(wohi, g_wohi) SYM(wolo, g_wolo)
    SYM(qhi, g_qhi) SYM(qlo, g_qlo) SYM(khi, g_khi) SYM(klo, g_klo)
    SYM(vhi, g_vhi) SYM(vlo, g_vlo) SYM(ohi, g_ohi) SYM(olo, g_olo)
    #undef SYM

    constexpr int GEMM_SMEM_A = 2 * (2 * 64 * 5 * 16 + 2 * 32 * 16 * 16);   // 53248
    constexpr int GEMM_SMEM_B = 2 * (2 * 128 * 5 * 16 + 2 * 32 * 8 * 16);   // 57344
    cudaFuncSetAttribute(gemm_bf3<64, 128, 1>,
                         cudaFuncAttributeMaxDynamicSharedMemorySize, GEMM_SMEM_A);
    cudaFuncSetAttribute(gemm_bf3<128, 64, 0>,
                         cudaFuncAttributeMaxDynamicSharedMemorySize, GEMM_SMEM_B);
    cudaFuncSetAttribute(flash_bf3,
                         cudaFuncAttributeMaxDynamicSharedMemorySize, FLASH_SMEM);

    split_inputs <<<dim3((16384 * 320 / 4 + 255) / 256, 2), 256>>>(
        (const float4*)x, (const float4*)ctx);
    split_weights<<<dim3((768 * 512 / 4 + 255) / 256, 4), 256>>>(
        (const float4*)Wq, (const float4*)Wk, (const float4*)Wv, (const float4*)Wo);

    // q-projection (scale = 0.125*log2e folded once here)
    gemm_bf3<64, 128, 1><<<dim3(4, 256, 1), 128, GEMM_SMEM_A>>>(
        (const bf16*)xhi, (const bf16*)xlo, (const bf16*)wqhi, (const bf16*)wqlo,
        nullptr, nullptr, nullptr, nullptr, (bf16*)qhi, (bf16*)qlo,
        nullptr, nullptr, 512, 320, N_, QSCALE_);
    // k- and v-projections merged (z selects weight/output set)
    gemm_bf3<64, 128, 1><<<dim3(4, 64, 2), 128, GEMM_SMEM_A>>>(
        (const bf16*)chi, (const bf16*)clo, (const bf16*)wkhi, (const bf16*)wklo,
        (const bf16*)wvhi, (const bf16*)wvlo, nullptr, nullptr,
        (bf16*)khi, (bf16*)klo, (bf16*)vhi, (bf16*)vlo, 512, 768, M_, 1.0f);

    // Attention
    flash_bf3<<<dim3(N_ / 128, H_, B_), 256, FLASH_SMEM>>>(
        (const bf16*)qhi, (const bf16*)qlo, (const bf16*)khi, (const bf16*)klo,
        (const bf16*)vhi, (const bf16*)vlo, (bf16*)ohi, (bf16*)olo);

    // Output projection
    gemm_bf3<128, 64, 0><<<dim3(5, 128, 1), 128, GEMM_SMEM_B>>>(
        (const bf16*)ohi, (const bf16*)olo, (const bf16*)wohi, (const bf16*)wolo,
        nullptr, nullptr, bo, out, nullptr, nullptr,
        nullptr, nullptr, 320, 512, 0, 1.0f);
}